// round 17
// baseline (speedup 1.0000x reference)
#include <cuda_runtime.h>
#include <math_constants.h>

// Problem constants (fixed by the dataset: B=32, N=2048)
#define BATCH 32
#define NPTS  2048
#define TPB   256
#define NWARP 8
#define ROWS  128                  // rows per (batch,chunk) pair
#define RPL   4                    // rows per lane
#define CHUNKS 16                  // row-chunks per batch
#define NQ    4                    // m-quarters
#define QPTS  (NPTS / NQ)          // 512 points per quarter
#define GRID  (BATCH * CHUNKS * NQ)  // 2048 blocks
#define PAIRS (BATCH * CHUNKS)       // 512 (batch,chunk) units
#define GPW   (QPTS / 4 / NWARP)     // 16 groups of 4 points per warp

__device__ unsigned g_rowmin[PAIRS][ROWS];   // ~bits(d), d >= 0; 0 == empty
__device__ double   g_partial[PAIRS];
__device__ int      g_pairdone[PAIRS];
__device__ unsigned g_done = 0;

typedef unsigned long long u64;

__device__ __forceinline__ u64 pack2(float lo, float hi) {
    u64 r;
    asm("mov.b64 %0, {%1, %2};" : "=l"(r) : "f"(lo), "f"(hi));
    return r;
}
__device__ __forceinline__ void unpack2(u64 v, float& lo, float& hi) {
    asm("mov.b64 {%0, %1}, %2;" : "=f"(lo), "=f"(hi) : "l"(v));
}
__device__ __forceinline__ u64 ffma2(u64 a, u64 b, u64 c) {
    u64 d;
    asm("fma.rn.f32x2 %0, %1, %2, %3;" : "=l"(d) : "l"(a), "l"(b), "l"(c));
    return d;
}

__device__ __forceinline__ void quat2mat(const float* __restrict__ q, float* R) {
    float w = q[0], x = q[1], y = q[2], z = q[3];
    float inv = 1.0f / sqrtf(w * w + x * x + y * y + z * z);
    w *= inv; x *= inv; y *= inv; z *= inv;
    R[0] = 1.f - 2.f * (y * y + z * z); R[1] = 2.f * (x * y - w * z); R[2] = 2.f * (x * z + w * y);
    R[3] = 2.f * (x * y + w * z);       R[4] = 1.f - 2.f * (x * x + z * z); R[5] = 2.f * (y * z - w * x);
    R[6] = 2.f * (x * z - w * y);       R[7] = 2.f * (y * z + w * x);       R[8] = 1.f - 2.f * (x * x + y * y);
}

__global__ void __launch_bounds__(TPB, 3)
pts_loss_kernel(const float* __restrict__ q_est,
                const float* __restrict__ q_gt,
                const float* __restrict__ pts,
                const int*   __restrict__ sym,
                float* __restrict__ out)
{
    const int bid     = blockIdx.x;
    const int b       = bid & 31;          // interleaved batch
    const int r2      = bid >> 5;
    const int chunk   = r2 & (CHUNKS - 1);
    const int quarter = r2 >> 4;
    const int pidx    = bid & (PAIRS - 1); // (batch, chunk) pair id
    const int tid     = threadIdx.x;
    const int wid     = tid >> 5;
    const int lid     = tid & 31;

    __shared__ __align__(16) float s_tab[QPTS * 4];   // 8 KB quarter table
    __shared__ float s_min[NWARP][ROWS];              // 4 KB
    __shared__ float s_red[TPB];
    __shared__ bool  s_fin;

    float Re[9], Rg[9];
    quat2mat(q_est + 4 * b, Re);
    quat2mat(q_gt  + 4 * b, Rg);

    const float* __restrict__ P = pts + (size_t)b * NPTS * 3;
    const bool is_sym = (sym[b] != 0);

    if (!is_sym) {
        // d_p handled only by quarter==0 block of the pair.
        if (quarter == 0) {
            float local = 0.0f;
            if (tid < ROWS) {
                float D[9];
                #pragma unroll
                for (int i = 0; i < 9; i++) D[i] = Re[i] - Rg[i];
                const int n = chunk * ROWS + tid;
                const float p0 = P[3 * n], p1 = P[3 * n + 1], p2 = P[3 * n + 2];
                const float e0 = D[0] * p0 + D[1] * p1 + D[2] * p2;
                const float e1 = D[3] * p0 + D[4] * p1 + D[5] * p2;
                const float e2 = D[6] * p0 + D[7] * p1 + D[8] * p2;
                local = e0 * e0 + e1 * e1 + e2 * e2;
            }
            s_red[tid] = local;
            __syncthreads();
            #pragma unroll
            for (int s = TPB / 2; s > 0; s >>= 1) {
                if (tid < s) s_red[tid] += s_red[tid + s];
                __syncthreads();
            }
            if (tid == 0) g_partial[pidx] = (double)s_red[0];
        }
    } else {
        // Relative rotation: Q = Re^T * Rg.  d(n,m) = nn_n + yy_m - 2 p_n . (Q p_m)
        float Q[9];
        #pragma unroll
        for (int i = 0; i < 3; i++)
            #pragma unroll
            for (int j = 0; j < 3; j++)
                Q[3 * i + j] = Re[i] * Rg[j] + Re[3 + i] * Rg[3 + j] + Re[6 + i] * Rg[6 + j];

        // ---- Build interleaved table for this m-quarter ----
        const int mbase = quarter * QPTS;
        #pragma unroll
        for (int k = 0; k < QPTS / TPB; k++) {
            const int i = tid + k * TPB;
            const int m = mbase + i;
            const float p0 = P[3 * m], p1 = P[3 * m + 1], p2 = P[3 * m + 2];
            const float y0 = Q[0] * p0 + Q[1] * p1 + Q[2] * p2;
            const float y1 = Q[3] * p0 + Q[4] * p1 + Q[5] * p2;
            const float y2 = Q[6] * p0 + Q[7] * p1 + Q[8] * p2;
            const int g = i >> 2, j = i & 3;
            float* t = s_tab + g * 16;
            t[j]      = -2.f * y0;
            t[j + 4]  = -2.f * y1;
            t[j + 8]  = -2.f * y2;
            t[j + 12] = y0 * y0 + y1 * y1 + y2 * y2;
        }

        // ---- Per-lane rows: raw points (no rotation needed!) ----
        u64 X0[RPL], X1[RPL], X2[RPL];
        #pragma unroll
        for (int r = 0; r < RPL; r++) {
            const int n = chunk * ROWS + lid + 32 * r;
            const float p0 = P[3 * n], p1 = P[3 * n + 1], p2 = P[3 * n + 2];
            X0[r] = pack2(p0, p0);
            X1[r] = pack2(p1, p1);
            X2[r] = pack2(p2, p2);
        }
        __syncthreads();

        float mn[RPL][4];
        #pragma unroll
        for (int r = 0; r < RPL; r++)
            #pragma unroll
            for (int k = 0; k < 4; k++) mn[r][k] = CUDART_INF_F;

        const ulonglong2* __restrict__ q = (const ulonglong2*)(s_tab + wid * (GPW * 16));

        #pragma unroll 2
        for (int g = 0; g < GPW; g++) {
            const ulonglong2 vx = q[g * 4 + 0];
            const ulonglong2 vy = q[g * 4 + 1];
            const ulonglong2 vz = q[g * 4 + 2];
            const ulonglong2 vw = q[g * 4 + 3];
            #pragma unroll
            for (int r = 0; r < RPL; r++) {
                float a, c, d, e;
                unpack2(ffma2(vx.x, X0[r], ffma2(vy.x, X1[r], ffma2(vz.x, X2[r], vw.x))), a, c);
                unpack2(ffma2(vx.y, X0[r], ffma2(vy.y, X1[r], ffma2(vz.y, X2[r], vw.y))), d, e);
                mn[r][0] = fminf(mn[r][0], a);
                mn[r][1] = fminf(mn[r][1], c);
                mn[r][2] = fminf(mn[r][2], d);
                mn[r][3] = fminf(mn[r][3], e);
            }
        }

        #pragma unroll
        for (int r = 0; r < RPL; r++)
            s_min[wid][lid + 32 * r] =
                fminf(fminf(mn[r][0], mn[r][1]), fminf(mn[r][2], mn[r][3]));
        __syncthreads();

        // Per-row min over 8 warps; ADD nn so the published value is the true
        // distance d >= 0, then publish via bit-ordered atomic max:
        // for d >= 0, bits are monotone, so min(d) == max(~bits(d)); 0-init == empty.
        if (tid < ROWS) {
            float mm = s_min[0][tid];
            #pragma unroll
            for (int w = 1; w < NWARP; w++) mm = fminf(mm, s_min[w][tid]);
            const int n = chunk * ROWS + tid;
            const float p0 = P[3 * n], p1 = P[3 * n + 1], p2 = P[3 * n + 2];
            const float nn = p0 * p0 + p1 * p1 + p2 * p2;
            const float dfull = fmaxf(nn + mm, 0.0f);  // clamp <=1e-7 rounding
            atomicMax(&g_rowmin[pidx][tid], ~__float_as_uint(dfull));
        }
        __syncthreads();

        // 4th-arriving quarter block finishes the pair.
        if (tid == 0) {
            __threadfence();
            s_fin = (atomicAdd(&g_pairdone[pidx], 1) == NQ - 1);
        }
        __syncthreads();

        if (s_fin) {
            __threadfence();
            float local = 0.0f;
            if (tid < ROWS) {
                local = __uint_as_float(~g_rowmin[pidx][tid]);
                g_rowmin[pidx][tid] = 0u;    // reset for next replay
            }
            s_red[tid] = local;
            __syncthreads();
            #pragma unroll
            for (int s = TPB / 2; s > 0; s >>= 1) {
                if (tid < s) s_red[tid] += s_red[tid + s];
                __syncthreads();
            }
            if (tid == 0) {
                g_partial[pidx] = (double)s_red[0];
                g_pairdone[pidx] = 0;        // reset for next replay
            }
        }
    }

    // ---- Finalize: last of all 2048 blocks sums the 512 pair partials ----
    __shared__ bool is_last;
    __shared__ double sd[TPB];
    if (tid == 0) {
        __threadfence();
        is_last = (atomicAdd(&g_done, 1u) == GRID - 1);
    }
    __syncthreads();

    if (is_last) {
        double acc = 0.0;
        #pragma unroll
        for (int i = 0; i < PAIRS / TPB; i++)
            acc += g_partial[tid + i * TPB];
        sd[tid] = acc;
        __syncthreads();
        #pragma unroll
        for (int s = TPB / 2; s > 0; s >>= 1) {
            if (tid < s) sd[tid] += sd[tid + s];
            __syncthreads();
        }
        if (tid == 0) {
            out[0] = (float)(sd[0] / (2.0 * (double)NPTS * (double)BATCH));
            g_done = 0;   // reset for next (graph-replayed) call
        }
    }
}

extern "C" void kernel_launch(void* const* d_in, const int* in_sizes, int n_in,
                              void* d_out, int out_size)
{
    // metadata order: q_est(32x4), q_gt(32x4), T(32x3, unused), pts(32x2048x3), symmetries(32x1 int32)
    const float* q_est = (const float*)d_in[0];
    const float* q_gt  = (const float*)d_in[1];
    const float* pts   = (const float*)d_in[3];
    const int*   sym   = (const int*)d_in[4];
    float* out = (float*)d_out;

    pts_loss_kernel<<<GRID, TPB>>>(q_est, q_gt, pts, sym, out);
}